// round 2
// baseline (speedup 1.0000x reference)
#include <cuda_runtime.h>

// Problem constants (fixed by the dataset)
#define Nn 50000
#define Ee 800000
#define Ff 128
#define Hh 256
#define Gg 512
#define Tt 5

// ---------------- scratch (device globals; no allocations allowed) ----------
__device__ int    g_cnt[Nn];
__device__ int    g_rowptr[Nn + 1];
__device__ int    g_cursor[Nn];
__device__ int    g_col[Ee];
__device__ float  g_dinv[Nn];
__device__ float4 g_bufA[(size_t)Nn * Hh / 4];   // ping  (features, scaled or raw)
__device__ float4 g_bufB[(size_t)Nn * Hh / 4];   // pong  (aggregation output)
__device__ float  g_pool[Gg * Hh];
__device__ float  g_cnts[Gg];

// ---------------- prep kernels ----------------------------------------------
__global__ void zero_kernel() {
    int i = blockIdx.x * blockDim.x + threadIdx.x;
    if (i < Nn) { g_cnt[i] = 0; g_cursor[i] = 0; }
    if (i < Gg * Hh) g_pool[i] = 0.0f;
    if (i < Gg) g_cnts[i] = 0.0f;
}

__global__ void hist_kernel(const int* __restrict__ dst) {
    int e = blockIdx.x * blockDim.x + threadIdx.x;
    if (e < Ee) {
        int d = dst[e];
        if (d >= 0 && d < Nn) atomicAdd(&g_cnt[d], 1);
    }
}

// Single-block chunked exclusive scan (warp-shuffle based), 49 chunks of 1024.
__global__ void scan_kernel() {
    __shared__ int warpsum[32];
    int tid = threadIdx.x, lane = tid & 31, wid = tid >> 5;
    int off = 0;
    for (int base = 0; base < Nn; base += 1024) {
        int i = base + tid;
        int orig = (i < Nn) ? g_cnt[i] : 0;
        int v = orig;
#pragma unroll
        for (int d = 1; d < 32; d <<= 1) {
            int t = __shfl_up_sync(0xffffffffu, v, d);
            if (lane >= d) v += t;
        }
        if (lane == 31) warpsum[wid] = v;
        __syncthreads();
        if (wid == 0) {
            int s = warpsum[lane];
#pragma unroll
            for (int d = 1; d < 32; d <<= 1) {
                int t = __shfl_up_sync(0xffffffffu, s, d);
                if (lane >= d) s += t;
            }
            warpsum[lane] = s;
        }
        __syncthreads();
        int prefix = (wid > 0) ? warpsum[wid - 1] : 0;
        int incl = v + prefix;
        if (i < Nn) g_rowptr[i] = off + incl - orig;
        int tot = warpsum[31];
        __syncthreads();             // protect warpsum reuse next chunk
        off += tot;
    }
    if (tid == 0) g_rowptr[Nn] = off;
}

__global__ void fill_kernel(const int* __restrict__ src,
                            const int* __restrict__ dst) {
    int e = blockIdx.x * blockDim.x + threadIdx.x;
    if (e < Ee) {
        int d = dst[e];
        int s = src[e];
        if (d >= 0 && d < Nn && s >= 0 && s < Nn) {
            int pos = g_rowptr[d] + atomicAdd(&g_cursor[d], 1);
            g_col[pos] = s;
        }
    }
}

__global__ void dinv_kernel() {
    int i = blockIdx.x * blockDim.x + threadIdx.x;
    if (i < Nn) g_dinv[i] = rsqrtf((float)(g_cnt[i] + 1));  // +1 self-loop
}

// xs = x * dinv[row]   (width Ff, into bufA)
__global__ void scale_x_kernel(const float4* __restrict__ x) {
    int idx = blockIdx.x * blockDim.x + threadIdx.x;   // over Nn * (Ff/4)
    if (idx < Nn * (Ff / 4)) {
        int row = idx / (Ff / 4);
        float d = g_dinv[row];
        float4 v = x[idx];
        v.x *= d; v.y *= d; v.z *= d; v.w *= d;
        g_bufA[idx] = v;
    }
}

// ---------------- aggregation: out[i] = dinv[i] * (hs[i] + sum_nbr hs[src]) --
// One warp per node. VPL = float4 per lane (1 for width 128, 2 for width 256).
template <int VPL>
__global__ void agg_kernel() {
    int warp = (blockIdx.x * blockDim.x + threadIdx.x) >> 5;
    int lane = threadIdx.x & 31;
    if (warp >= Nn) return;
    const int W4 = VPL * 32;
    const float4* __restrict__ hs = g_bufA;
    float4* __restrict__ out = g_bufB;

    float4 acc[VPL];
#pragma unroll
    for (int v = 0; v < VPL; v++)
        acc[v] = hs[(size_t)warp * W4 + v * 32 + lane];   // self-loop term

    int beg = g_rowptr[warp], end = g_rowptr[warp + 1];
    int e = beg;
    for (; e + 1 < end; e += 2) {
        int s0 = g_col[e], s1 = g_col[e + 1];
#pragma unroll
        for (int v = 0; v < VPL; v++) {
            float4 t0 = hs[(size_t)s0 * W4 + v * 32 + lane];
            float4 t1 = hs[(size_t)s1 * W4 + v * 32 + lane];
            acc[v].x += t0.x + t1.x; acc[v].y += t0.y + t1.y;
            acc[v].z += t0.z + t1.z; acc[v].w += t0.w + t1.w;
        }
    }
    if (e < end) {
        int s0 = g_col[e];
#pragma unroll
        for (int v = 0; v < VPL; v++) {
            float4 t0 = hs[(size_t)s0 * W4 + v * 32 + lane];
            acc[v].x += t0.x; acc[v].y += t0.y; acc[v].z += t0.z; acc[v].w += t0.w;
        }
    }
    float di = g_dinv[warp];
#pragma unroll
    for (int v = 0; v < VPL; v++) {
        acc[v].x *= di; acc[v].y *= di; acc[v].z *= di; acc[v].w *= di;
        out[(size_t)warp * W4 + v * 32 + lane] = acc[v];
    }
}

// ---------------- GEMM: bufA = epi( bufB[N x K] @ W[K x 256] + b ) -----------
// epi = relu, then optionally * dinv[row] (pre-scale for next aggregation)
#define BM 128
#define BN 128
#define BKK 8
__global__ __launch_bounds__(256)
void gemm_kernel(const float* __restrict__ W, const float* __restrict__ bias,
                 int K, int scaleFlag) {
    __shared__ float As[BKK][BM];
    __shared__ float Bs[BKK][BN];
    const float* __restrict__ A = (const float*)g_bufB;
    float* __restrict__ C = (float*)g_bufA;

    int tid = threadIdx.x;
    int tx = tid & 15, ty = tid >> 4;
    int rowBase = blockIdx.x * BM;
    int colBase = blockIdx.y * BN;

    int aRow = tid >> 1;            // 0..127
    int aCol = (tid & 1) * 4;       // 0 or 4
    int bRow = tid >> 5;            // 0..7
    int bCol = (tid & 31) * 4;      // 0..124

    float acc[8][8];
#pragma unroll
    for (int i = 0; i < 8; i++)
#pragma unroll
        for (int j = 0; j < 8; j++) acc[i][j] = 0.0f;

    for (int k0 = 0; k0 < K; k0 += BKK) {
        float4 av = make_float4(0.f, 0.f, 0.f, 0.f);
        int gr = rowBase + aRow;
        if (gr < Nn) av = *(const float4*)(A + (size_t)gr * K + k0 + aCol);
        As[aCol + 0][aRow] = av.x;
        As[aCol + 1][aRow] = av.y;
        As[aCol + 2][aRow] = av.z;
        As[aCol + 3][aRow] = av.w;
        float4 bv = *(const float4*)(W + (size_t)(k0 + bRow) * Hh + colBase + bCol);
        *(float4*)(&Bs[bRow][bCol]) = bv;
        __syncthreads();
#pragma unroll
        for (int kk = 0; kk < BKK; kk++) {
            float af[8], bf[8];
#pragma unroll
            for (int i = 0; i < 8; i++) af[i] = As[kk][ty * 8 + i];
#pragma unroll
            for (int j = 0; j < 8; j++) bf[j] = Bs[kk][tx * 8 + j];
#pragma unroll
            for (int i = 0; i < 8; i++)
#pragma unroll
                for (int j = 0; j < 8; j++) acc[i][j] += af[i] * bf[j];
        }
        __syncthreads();
    }

#pragma unroll
    for (int i = 0; i < 8; i++) {
        int r = rowBase + ty * 8 + i;
        if (r >= Nn) continue;
        float sc = scaleFlag ? g_dinv[r] : 1.0f;
#pragma unroll
        for (int j = 0; j < 8; j++) {
            int c = colBase + tx * 8 + j;
            float v = acc[i][j] + bias[c];
            v = fmaxf(v, 0.0f);
            C[(size_t)r * Hh + c] = v * sc;
        }
    }
}

// ---------------- pooling + output head -------------------------------------
__global__ void pool_kernel(const int* __restrict__ batch) {
    int i = blockIdx.x;                    // node
    int g = batch[i];
    if (g < 0 || g >= Gg) return;
    const float4* row = g_bufA + (size_t)i * (Hh / 4);
    float4 v = row[threadIdx.x];
    int c = threadIdx.x * 4;
    atomicAdd(&g_pool[g * Hh + c + 0], v.x);
    atomicAdd(&g_pool[g * Hh + c + 1], v.y);
    atomicAdd(&g_pool[g * Hh + c + 2], v.z);
    atomicAdd(&g_pool[g * Hh + c + 3], v.w);
    if (threadIdx.x == 0) atomicAdd(&g_cnts[g], 1.0f);
}

__global__ void out_kernel(const float* __restrict__ Wout,
                           const float* __restrict__ bout,
                           float* __restrict__ out) {
    int g = blockIdx.x;
    int lane = threadIdx.x;                 // 32 threads
    float inv = 1.0f / fmaxf(g_cnts[g], 1.0f);
    float p[8];
#pragma unroll
    for (int v = 0; v < 8; v++) p[v] = g_pool[g * Hh + v * 32 + lane] * inv;
#pragma unroll
    for (int t = 0; t < Tt; t++) {
        float s = 0.0f;
#pragma unroll
        for (int v = 0; v < 8; v++) s += p[v] * Wout[(v * 32 + lane) * Tt + t];
#pragma unroll
        for (int off = 16; off; off >>= 1) s += __shfl_down_sync(0xffffffffu, s, off);
        if (lane == 0) out[g * Tt + t] = s + bout[t];
    }
}

// ---------------- launch -----------------------------------------------------
extern "C" void kernel_launch(void* const* d_in, const int* in_sizes, int n_in,
                              void* d_out, int out_size) {
    const float* x    = (const float*)d_in[0];
    const int*   ei   = (const int*)d_in[1];   // [2, E] int32 (JAX x64 disabled)
    const int*   bat  = (const int*)d_in[2];
    const float* W0 = (const float*)d_in[3];  const float* b0 = (const float*)d_in[4];
    const float* W1 = (const float*)d_in[5];  const float* b1 = (const float*)d_in[6];
    const float* W2 = (const float*)d_in[7];  const float* b2 = (const float*)d_in[8];
    const float* W3 = (const float*)d_in[9];  const float* b3 = (const float*)d_in[10];
    const float* Wout = (const float*)d_in[11]; const float* bout = (const float*)d_in[12];
    float* out = (float*)d_out;

    const int* src = ei;
    const int* dst = ei + Ee;

    // prep
    zero_kernel<<<(Gg * Hh + 255) / 256, 256>>>();
    hist_kernel<<<(Ee + 255) / 256, 256>>>(dst);
    scan_kernel<<<1, 1024>>>();
    fill_kernel<<<(Ee + 255) / 256, 256>>>(src, dst);
    dinv_kernel<<<(Nn + 255) / 256, 256>>>();
    scale_x_kernel<<<(Nn * (Ff / 4) + 255) / 256, 256>>>((const float4*)x);

    dim3 gemmGrid((Nn + BM - 1) / BM, Hh / BN);
    int aggBlocks = (Nn * 32 + 255) / 256;

    // layer 0 (K=128)
    agg_kernel<1><<<aggBlocks, 256>>>();
    gemm_kernel<<<gemmGrid, 256>>>(W0, b0, Ff, 1);
    // layer 1
    agg_kernel<2><<<aggBlocks, 256>>>();
    gemm_kernel<<<gemmGrid, 256>>>(W1, b1, Hh, 1);
    // layer 2
    agg_kernel<2><<<aggBlocks, 256>>>();
    gemm_kernel<<<gemmGrid, 256>>>(W2, b2, Hh, 1);
    // layer 3 (no dinv pre-scale: pooling wants raw h)
    agg_kernel<2><<<aggBlocks, 256>>>();
    gemm_kernel<<<gemmGrid, 256>>>(W3, b3, Hh, 0);

    // mean pool + head
    pool_kernel<<<Nn, Hh / 4>>>(bat);
    out_kernel<<<Gg, 32>>>(Wout, bout, out);
}

// round 3
// speedup vs baseline: 1.8738x; 1.8738x over previous
#include <cuda_runtime.h>

// Problem constants (fixed by the dataset)
#define Nn 50000
#define Ee 800000
#define Ff 128
#define Hh 256
#define Gg 512
#define Tt 5

// ---------------- scratch (device globals; no allocations allowed) ----------
__device__ int    g_cnt[Nn];
__device__ int    g_rowptr[Nn + 1];
__device__ int    g_cursor[Nn];
__device__ int    g_col[Ee];
__device__ float  g_dinv[Nn];
__device__ float4 g_bufA[(size_t)Nn * Hh / 4];   // ping  (features, scaled or raw)
__device__ float4 g_bufB[(size_t)Nn * Hh / 4];   // pong  (aggregation output)
__device__ float  g_pool[Gg * Hh];
__device__ float  g_cnts[Gg];

// ---------------- prep kernels ----------------------------------------------
__global__ void zero_kernel() {
    int i = blockIdx.x * blockDim.x + threadIdx.x;
    if (i < Nn) { g_cnt[i] = 0; g_cursor[i] = 0; }
    if (i < Gg * Hh) g_pool[i] = 0.0f;
    if (i < Gg) g_cnts[i] = 0.0f;
}

__global__ void hist_kernel(const int* __restrict__ dst) {
    int e = blockIdx.x * blockDim.x + threadIdx.x;
    if (e < Ee) {
        int d = dst[e];
        if (d >= 0 && d < Nn) atomicAdd(&g_cnt[d], 1);
    }
}

// Single-block chunked exclusive scan (warp-shuffle based), 49 chunks of 1024.
__global__ void scan_kernel() {
    __shared__ int warpsum[32];
    int tid = threadIdx.x, lane = tid & 31, wid = tid >> 5;
    int off = 0;
    for (int base = 0; base < Nn; base += 1024) {
        int i = base + tid;
        int orig = (i < Nn) ? g_cnt[i] : 0;
        int v = orig;
#pragma unroll
        for (int d = 1; d < 32; d <<= 1) {
            int t = __shfl_up_sync(0xffffffffu, v, d);
            if (lane >= d) v += t;
        }
        if (lane == 31) warpsum[wid] = v;
        __syncthreads();
        if (wid == 0) {
            int s = warpsum[lane];
#pragma unroll
            for (int d = 1; d < 32; d <<= 1) {
                int t = __shfl_up_sync(0xffffffffu, s, d);
                if (lane >= d) s += t;
            }
            warpsum[lane] = s;
        }
        __syncthreads();
        int prefix = (wid > 0) ? warpsum[wid - 1] : 0;
        int incl = v + prefix;
        if (i < Nn) g_rowptr[i] = off + incl - orig;
        int tot = warpsum[31];
        __syncthreads();             // protect warpsum reuse next chunk
        off += tot;
    }
    if (tid == 0) g_rowptr[Nn] = off;
}

__global__ void fill_kernel(const int* __restrict__ src,
                            const int* __restrict__ dst) {
    int e = blockIdx.x * blockDim.x + threadIdx.x;
    if (e < Ee) {
        int d = dst[e];
        int s = src[e];
        if (d >= 0 && d < Nn && s >= 0 && s < Nn) {
            int pos = g_rowptr[d] + atomicAdd(&g_cursor[d], 1);
            g_col[pos] = s;
        }
    }
}

// dinv + per-graph node counts
__global__ void dinv_kernel(const int* __restrict__ batch) {
    int i = blockIdx.x * blockDim.x + threadIdx.x;
    if (i < Nn) {
        g_dinv[i] = rsqrtf((float)(g_cnt[i] + 1));  // +1 self-loop
        int g = batch[i];
        if (g >= 0 && g < Gg) atomicAdd(&g_cnts[g], 1.0f);
    }
}

// xs = x * dinv[row]   (width Ff, into bufA)
__global__ void scale_x_kernel(const float4* __restrict__ x) {
    int idx = blockIdx.x * blockDim.x + threadIdx.x;   // over Nn * (Ff/4)
    if (idx < Nn * (Ff / 4)) {
        int row = idx / (Ff / 4);
        float d = g_dinv[row];
        float4 v = x[idx];
        v.x *= d; v.y *= d; v.z *= d; v.w *= d;
        g_bufA[idx] = v;
    }
}

// ---------------- aggregation: out[i] = dinv[i] * (hs[i] + sum_nbr hs[src]) --
// One warp per node. VPL = float4 per lane (1 for width 128, 2 for width 256).
template <int VPL>
__global__ void agg_kernel() {
    int warp = (blockIdx.x * blockDim.x + threadIdx.x) >> 5;
    int lane = threadIdx.x & 31;
    if (warp >= Nn) return;
    const int W4 = VPL * 32;
    const float4* __restrict__ hs = g_bufA;
    float4* __restrict__ out = g_bufB;

    float4 acc[VPL];
#pragma unroll
    for (int v = 0; v < VPL; v++)
        acc[v] = hs[(size_t)warp * W4 + v * 32 + lane];   // self-loop term

    int beg = g_rowptr[warp], end = g_rowptr[warp + 1];
    int e = beg;
    for (; e + 1 < end; e += 2) {
        int s0 = g_col[e], s1 = g_col[e + 1];
#pragma unroll
        for (int v = 0; v < VPL; v++) {
            float4 t0 = hs[(size_t)s0 * W4 + v * 32 + lane];
            float4 t1 = hs[(size_t)s1 * W4 + v * 32 + lane];
            acc[v].x += t0.x + t1.x; acc[v].y += t0.y + t1.y;
            acc[v].z += t0.z + t1.z; acc[v].w += t0.w + t1.w;
        }
    }
    if (e < end) {
        int s0 = g_col[e];
#pragma unroll
        for (int v = 0; v < VPL; v++) {
            float4 t0 = hs[(size_t)s0 * W4 + v * 32 + lane];
            acc[v].x += t0.x; acc[v].y += t0.y; acc[v].z += t0.z; acc[v].w += t0.w;
        }
    }
    float di = g_dinv[warp];
#pragma unroll
    for (int v = 0; v < VPL; v++) {
        acc[v].x *= di; acc[v].y *= di; acc[v].z *= di; acc[v].w *= di;
        out[(size_t)warp * W4 + v * 32 + lane] = acc[v];
    }
}

// ---------------- TF32 tensor-core GEMM --------------------------------------
// bufA = epi( bufB[N x K] @ W[K x 256] + b ),  epi = relu then optional *dinv
// poolFlag: instead of storing, atomicAdd into g_pool[batch[row]] (layer 3).
#define BM 128
#define BN 128
#define BKT 16
#define SSTR 136   // smem row stride (words); 136 % 32 == 8 -> conflict-free frags

__device__ __forceinline__ unsigned f2tf32(float f) {
    unsigned u;
    asm("cvt.rna.tf32.f32 %0, %1;" : "=r"(u) : "f"(f));
    return u;
}

__device__ __forceinline__ void mma_tf32(float* c, const unsigned* a, const unsigned* b) {
    asm volatile(
        "mma.sync.aligned.m16n8k8.row.col.f32.tf32.tf32.f32 "
        "{%0,%1,%2,%3}, {%4,%5,%6,%7}, {%8,%9}, {%0,%1,%2,%3};"
        : "+f"(c[0]), "+f"(c[1]), "+f"(c[2]), "+f"(c[3])
        : "r"(a[0]), "r"(a[1]), "r"(a[2]), "r"(a[3]), "r"(b[0]), "r"(b[1]));
}

__global__ __launch_bounds__(256)
void gemm_tf32_kernel(const float* __restrict__ W, const float* __restrict__ bias,
                      int K, int scaleFlag, int poolFlag,
                      const int* __restrict__ batch) {
    __shared__ unsigned As[BKT][SSTR];   // transposed: As[k][m], tf32 bits
    __shared__ unsigned Bs[BKT][SSTR];   // Bs[k][n], tf32 bits

    const float* __restrict__ A = (const float*)g_bufB;
    float* __restrict__ C = (float*)g_bufA;

    int tid = threadIdx.x;
    int warpId = tid >> 5, lane = tid & 31;
    int g = lane >> 2, q = lane & 3;
    int warpM = warpId >> 2;          // 0..1  -> 64 rows each
    int warpN = warpId & 3;           // 0..3  -> 32 cols each
    int rowBase = blockIdx.x * BM;
    int colBase = blockIdx.y * BN;

    float acc[4][4][4];
#pragma unroll
    for (int mt = 0; mt < 4; mt++)
#pragma unroll
        for (int nt = 0; nt < 4; nt++)
#pragma unroll
            for (int i = 0; i < 4; i++) acc[mt][nt][i] = 0.0f;

    // A-load indices: each thread loads 2 float4 of one row-half
    int aRow = tid >> 1;              // 0..127
    int aK   = (tid & 1) * 8;         // 0 or 8
    // B-load indices: each thread loads 2 float4 (rows k and k+8)
    int bK = tid >> 5;                // 0..7
    int bN = (tid & 31) * 4;          // 0..124

    for (int k0 = 0; k0 < K; k0 += BKT) {
        // ---- load A tile, transpose, convert to tf32 ----
        int gr = rowBase + aRow;
        float4 v0 = make_float4(0.f, 0.f, 0.f, 0.f), v1 = v0;
        if (gr < Nn) {
            const float* ap = A + (size_t)gr * K + k0 + aK;
            v0 = *(const float4*)(ap);
            v1 = *(const float4*)(ap + 4);
        }
        As[aK + 0][aRow] = f2tf32(v0.x);
        As[aK + 1][aRow] = f2tf32(v0.y);
        As[aK + 2][aRow] = f2tf32(v0.z);
        As[aK + 3][aRow] = f2tf32(v0.w);
        As[aK + 4][aRow] = f2tf32(v1.x);
        As[aK + 5][aRow] = f2tf32(v1.y);
        As[aK + 6][aRow] = f2tf32(v1.z);
        As[aK + 7][aRow] = f2tf32(v1.w);
        // ---- load B tile, convert to tf32 ----
        float4 w0 = *(const float4*)(W + (size_t)(k0 + bK) * Hh + colBase + bN);
        float4 w1 = *(const float4*)(W + (size_t)(k0 + bK + 8) * Hh + colBase + bN);
        Bs[bK][bN + 0] = f2tf32(w0.x);
        Bs[bK][bN + 1] = f2tf32(w0.y);
        Bs[bK][bN + 2] = f2tf32(w0.z);
        Bs[bK][bN + 3] = f2tf32(w0.w);
        Bs[bK + 8][bN + 0] = f2tf32(w1.x);
        Bs[bK + 8][bN + 1] = f2tf32(w1.y);
        Bs[bK + 8][bN + 2] = f2tf32(w1.z);
        Bs[bK + 8][bN + 3] = f2tf32(w1.w);
        __syncthreads();

#pragma unroll
        for (int kk = 0; kk < 2; kk++) {
            unsigned afr[4][4];
#pragma unroll
            for (int mt = 0; mt < 4; mt++) {
                int m = warpM * 64 + mt * 16;
                afr[mt][0] = As[kk * 8 + q][m + g];
                afr[mt][1] = As[kk * 8 + q][m + g + 8];
                afr[mt][2] = As[kk * 8 + q + 4][m + g];
                afr[mt][3] = As[kk * 8 + q + 4][m + g + 8];
            }
#pragma unroll
            for (int nt = 0; nt < 4; nt++) {
                int n = warpN * 32 + nt * 8;
                unsigned bfr[2];
                bfr[0] = Bs[kk * 8 + q][n + g];
                bfr[1] = Bs[kk * 8 + q + 4][n + g];
#pragma unroll
                for (int mt = 0; mt < 4; mt++)
                    mma_tf32(acc[mt][nt], afr[mt], bfr);
            }
        }
        __syncthreads();
    }

    // ---- epilogue ----
#pragma unroll
    for (int mt = 0; mt < 4; mt++) {
        int r0 = rowBase + warpM * 64 + mt * 16 + g;
        int r1 = r0 + 8;
        bool ok0 = r0 < Nn, ok1 = r1 < Nn;
        float sc0 = (ok0 && scaleFlag) ? g_dinv[r0] : 1.0f;
        float sc1 = (ok1 && scaleFlag) ? g_dinv[r1] : 1.0f;
        int gb0 = (ok0 && poolFlag) ? batch[r0] : 0;
        int gb1 = (ok1 && poolFlag) ? batch[r1] : 0;
#pragma unroll
        for (int nt = 0; nt < 4; nt++) {
            int c = colBase + warpN * 32 + nt * 8 + 2 * q;
            float bs0 = bias[c], bs1 = bias[c + 1];
            float v00 = fmaxf(acc[mt][nt][0] + bs0, 0.0f) * sc0;
            float v01 = fmaxf(acc[mt][nt][1] + bs1, 0.0f) * sc0;
            float v10 = fmaxf(acc[mt][nt][2] + bs0, 0.0f) * sc1;
            float v11 = fmaxf(acc[mt][nt][3] + bs1, 0.0f) * sc1;
            if (poolFlag) {
                if (ok0) {
                    atomicAdd(&g_pool[gb0 * Hh + c], v00);
                    atomicAdd(&g_pool[gb0 * Hh + c + 1], v01);
                }
                if (ok1) {
                    atomicAdd(&g_pool[gb1 * Hh + c], v10);
                    atomicAdd(&g_pool[gb1 * Hh + c + 1], v11);
                }
            } else {
                if (ok0) *(float2*)(C + (size_t)r0 * Hh + c) = make_float2(v00, v01);
                if (ok1) *(float2*)(C + (size_t)r1 * Hh + c) = make_float2(v10, v11);
            }
        }
    }
}

// ---------------- output head -------------------------------------------------
__global__ void out_kernel(const float* __restrict__ Wout,
                           const float* __restrict__ bout,
                           float* __restrict__ out) {
    int g = blockIdx.x;
    int lane = threadIdx.x;                 // 32 threads
    float inv = 1.0f / fmaxf(g_cnts[g], 1.0f);
    float p[8];
#pragma unroll
    for (int v = 0; v < 8; v++) p[v] = g_pool[g * Hh + v * 32 + lane] * inv;
#pragma unroll
    for (int t = 0; t < Tt; t++) {
        float s = 0.0f;
#pragma unroll
        for (int v = 0; v < 8; v++) s += p[v] * Wout[(v * 32 + lane) * Tt + t];
#pragma unroll
        for (int off = 16; off; off >>= 1) s += __shfl_down_sync(0xffffffffu, s, off);
        if (lane == 0) out[g * Tt + t] = s + bout[t];
    }
}

// ---------------- launch -----------------------------------------------------
extern "C" void kernel_launch(void* const* d_in, const int* in_sizes, int n_in,
                              void* d_out, int out_size) {
    const float* x    = (const float*)d_in[0];
    const int*   ei   = (const int*)d_in[1];   // [2, E] int32
    const int*   bat  = (const int*)d_in[2];
    const float* W0 = (const float*)d_in[3];  const float* b0 = (const float*)d_in[4];
    const float* W1 = (const float*)d_in[5];  const float* b1 = (const float*)d_in[6];
    const float* W2 = (const float*)d_in[7];  const float* b2 = (const float*)d_in[8];
    const float* W3 = (const float*)d_in[9];  const float* b3 = (const float*)d_in[10];
    const float* Wout = (const float*)d_in[11]; const float* bout = (const float*)d_in[12];
    float* out = (float*)d_out;

    const int* src = ei;
    const int* dst = ei + Ee;

    // prep
    zero_kernel<<<(Gg * Hh + 255) / 256, 256>>>();
    hist_kernel<<<(Ee + 255) / 256, 256>>>(dst);
    scan_kernel<<<1, 1024>>>();
    fill_kernel<<<(Ee + 255) / 256, 256>>>(src, dst);
    dinv_kernel<<<(Nn + 255) / 256, 256>>>(bat);
    scale_x_kernel<<<(Nn * (Ff / 4) + 255) / 256, 256>>>((const float4*)x);

    dim3 gemmGrid((Nn + BM - 1) / BM, Hh / BN);
    int aggBlocks = (Nn * 32 + 255) / 256;

    // layer 0 (K=128)
    agg_kernel<1><<<aggBlocks, 256>>>();
    gemm_tf32_kernel<<<gemmGrid, 256>>>(W0, b0, Ff, 1, 0, bat);
    // layer 1
    agg_kernel<2><<<aggBlocks, 256>>>();
    gemm_tf32_kernel<<<gemmGrid, 256>>>(W1, b1, Hh, 1, 0, bat);
    // layer 2
    agg_kernel<2><<<aggBlocks, 256>>>();
    gemm_tf32_kernel<<<gemmGrid, 256>>>(W2, b2, Hh, 1, 0, bat);
    // layer 3: no dinv pre-scale; fused mean-pool accumulation
    agg_kernel<2><<<aggBlocks, 256>>>();
    gemm_tf32_kernel<<<gemmGrid, 256>>>(W3, b3, Hh, 0, 1, bat);

    // head
    out_kernel<<<Gg, 32>>>(Wout, bout, out);
}

// round 4
// speedup vs baseline: 2.8585x; 1.5256x over previous
#include <cuda_runtime.h>
#include <cuda_fp16.h>

// Problem constants (fixed by the dataset)
#define Nn 50000
#define Ee 800000
#define Ff 128
#define Hh 256
#define Gg 512
#define Tt 5

#define NBLK 196   // ceil(Nn/256) scan blocks

// ---------------- scratch (device globals; no allocations allowed) ----------
__device__ int    g_cnt[Nn];
__device__ int    g_rowptr[Nn + 1];
__device__ int    g_cursor[Nn];
__device__ int    g_col[Ee];
__device__ float  g_dinv[Nn];
__device__ int    g_bsum[NBLK];
__device__ int    g_boff[NBLK];
__device__ __half g_bufA[(size_t)Nn * Hh];   // ping (features, fp16)
__device__ __half g_bufB[(size_t)Nn * Hh];   // pong (aggregation output, fp16)
__device__ float  g_pool[Gg * Hh];
__device__ float  g_cnts[Gg];

// ---------------- prep kernels ----------------------------------------------
__global__ void zero_kernel() {
    int i = blockIdx.x * blockDim.x + threadIdx.x;
    if (i < Nn) { g_cnt[i] = 0; g_cursor[i] = 0; }
    if (i < Gg * Hh) g_pool[i] = 0.0f;
    if (i < Gg) g_cnts[i] = 0.0f;
}

__global__ void hist_kernel(const int* __restrict__ dst) {
    int e = blockIdx.x * blockDim.x + threadIdx.x;
    if (e < Ee) {
        int d = dst[e];
        if (d >= 0 && d < Nn) atomicAdd(&g_cnt[d], 1);
    }
}

// hierarchical scan: block sums -> scan sums -> per-block rescan
__global__ void scan1_kernel() {
    __shared__ int wsum[8];
    int tid = threadIdx.x, lane = tid & 31, wid = tid >> 5;
    int i = blockIdx.x * 256 + tid;
    int v = (i < Nn) ? g_cnt[i] : 0;
#pragma unroll
    for (int d = 16; d; d >>= 1) v += __shfl_down_sync(0xffffffffu, v, d);
    if (lane == 0) wsum[wid] = v;
    __syncthreads();
    if (tid == 0) {
        int s = 0;
#pragma unroll
        for (int w = 0; w < 8; w++) s += wsum[w];
        g_bsum[blockIdx.x] = s;
    }
}

__global__ void scan2_kernel() {
    __shared__ int s[256];
    int tid = threadIdx.x;
    int v = (tid < NBLK) ? g_bsum[tid] : 0;
    s[tid] = v;
    __syncthreads();
    for (int d = 1; d < 256; d <<= 1) {
        int t = (tid >= d) ? s[tid - d] : 0;
        __syncthreads();
        s[tid] += t;
        __syncthreads();
    }
    if (tid < NBLK) g_boff[tid] = s[tid] - v;   // exclusive
    if (tid == NBLK - 1) g_rowptr[Nn] = s[tid];
}

__global__ void scan3_kernel() {
    __shared__ int wsum[8];
    int tid = threadIdx.x, lane = tid & 31, wid = tid >> 5;
    int i = blockIdx.x * 256 + tid;
    int orig = (i < Nn) ? g_cnt[i] : 0;
    int v = orig;
#pragma unroll
    for (int d = 1; d < 32; d <<= 1) {
        int t = __shfl_up_sync(0xffffffffu, v, d);
        if (lane >= d) v += t;
    }
    if (lane == 31) wsum[wid] = v;
    __syncthreads();
    if (wid == 0 && lane < 8) {
        int s = wsum[lane];
#pragma unroll
        for (int d = 1; d < 8; d <<= 1) {
            int t = __shfl_up_sync(0x000000ffu, s, d);
            if (lane >= d) s += t;
        }
        wsum[lane] = s;
    }
    __syncthreads();
    int prefix = (wid > 0) ? wsum[wid - 1] : 0;
    if (i < Nn) g_rowptr[i] = g_boff[blockIdx.x] + prefix + v - orig;
}

__global__ void fill_kernel(const int* __restrict__ src,
                            const int* __restrict__ dst) {
    int e = blockIdx.x * blockDim.x + threadIdx.x;
    if (e < Ee) {
        int d = dst[e];
        int s = src[e];
        if (d >= 0 && d < Nn && s >= 0 && s < Nn) {
            int pos = g_rowptr[d] + atomicAdd(&g_cursor[d], 1);
            g_col[pos] = s;
        }
    }
}

// dinv + per-graph node counts
__global__ void dinv_kernel(const int* __restrict__ batch) {
    int i = blockIdx.x * blockDim.x + threadIdx.x;
    if (i < Nn) {
        g_dinv[i] = rsqrtf((float)(g_cnt[i] + 1));  // +1 self-loop
        int g = batch[i];
        if (g >= 0 && g < Gg) atomicAdd(&g_cnts[g], 1.0f);
    }
}

// bufA(fp16) = x * dinv[row]   (width Ff); each thread handles 8 floats
__global__ void scale_x_kernel(const float4* __restrict__ x) {
    int idx = blockIdx.x * blockDim.x + threadIdx.x;   // over Nn * 16
    if (idx < Nn * (Ff / 8)) {
        int row = idx >> 4;
        float d = g_dinv[row];
        float4 v0 = x[idx * 2], v1 = x[idx * 2 + 1];
        __half2 h[4];
        h[0] = __floats2half2_rn(v0.x * d, v0.y * d);
        h[1] = __floats2half2_rn(v0.z * d, v0.w * d);
        h[2] = __floats2half2_rn(v1.x * d, v1.y * d);
        h[3] = __floats2half2_rn(v1.z * d, v1.w * d);
        ((uint4*)g_bufA)[idx] = *(uint4*)h;
    }
}

// ---------------- aggregation (fp16 in, fp32 accum, fp16 out) ---------------
// One warp per node. VH halves per lane (4 for width 128, 8 for width 256).
template <int UC> struct VecT;
template <> struct VecT<2> { using T = uint2; };
template <> struct VecT<4> { using T = uint4; };

template <int VH>
__global__ void agg_kernel() {
    constexpr int UC = VH / 2;
    using V = typename VecT<UC>::T;
    int warp = (blockIdx.x * blockDim.x + threadIdx.x) >> 5;
    int lane = threadIdx.x & 31;
    if (warp >= Nn) return;
    const V* __restrict__ hs = (const V*)g_bufA;   // row = 32 V units
    V* __restrict__ outp = (V*)g_bufB;

    float f[VH];
    {
        V v = hs[(size_t)warp * 32 + lane];        // self-loop term
        const unsigned* u = (const unsigned*)&v;
#pragma unroll
        for (int h = 0; h < UC; h++) {
            float2 p = __half22float2(*(const __half2*)&u[h]);
            f[2 * h] = p.x; f[2 * h + 1] = p.y;
        }
    }

    int beg = g_rowptr[warp], end = g_rowptr[warp + 1];
    int e = beg;
    for (; e + 1 < end; e += 2) {
        int s0 = g_col[e], s1 = g_col[e + 1];
        V v0 = hs[(size_t)s0 * 32 + lane];
        V v1 = hs[(size_t)s1 * 32 + lane];
        const unsigned* u0 = (const unsigned*)&v0;
        const unsigned* u1 = (const unsigned*)&v1;
#pragma unroll
        for (int h = 0; h < UC; h++) {
            float2 p0 = __half22float2(*(const __half2*)&u0[h]);
            float2 p1 = __half22float2(*(const __half2*)&u1[h]);
            f[2 * h] += p0.x + p1.x;
            f[2 * h + 1] += p0.y + p1.y;
        }
    }
    if (e < end) {
        int s0 = g_col[e];
        V v0 = hs[(size_t)s0 * 32 + lane];
        const unsigned* u0 = (const unsigned*)&v0;
#pragma unroll
        for (int h = 0; h < UC; h++) {
            float2 p0 = __half22float2(*(const __half2*)&u0[h]);
            f[2 * h] += p0.x;
            f[2 * h + 1] += p0.y;
        }
    }
    float di = g_dinv[warp];
    V ov;
    unsigned* ou = (unsigned*)&ov;
#pragma unroll
    for (int h = 0; h < UC; h++) {
        __half2 p = __floats2half2_rn(f[2 * h] * di, f[2 * h + 1] * di);
        ou[h] = *(unsigned*)&p;
    }
    outp[(size_t)warp * 32 + lane] = ov;
}

// ---------------- fp16 tensor-core GEMM --------------------------------------
// bufA = epi( bufB[N x K](fp16) @ W[K x 256] + b );  epi = relu, optional *dinv
// poolFlag: atomicAdd into g_pool[batch[row]] instead of storing (layer 3).
#define BM 128
#define BN 128
#define BK 32
#define ASTR 40    // smem row stride in halves; conflict-free fragment loads

__device__ __forceinline__ void mma_f16(float* c, const unsigned* a, const unsigned* b) {
    asm volatile(
        "mma.sync.aligned.m16n8k16.row.col.f32.f16.f16.f32 "
        "{%0,%1,%2,%3}, {%4,%5,%6,%7}, {%8,%9}, {%0,%1,%2,%3};"
        : "+f"(c[0]), "+f"(c[1]), "+f"(c[2]), "+f"(c[3])
        : "r"(a[0]), "r"(a[1]), "r"(a[2]), "r"(a[3]), "r"(b[0]), "r"(b[1]));
}

__global__ __launch_bounds__(256)
void gemm_f16_kernel(const float* __restrict__ W, const float* __restrict__ bias,
                     int K, int scaleFlag, int poolFlag,
                     const int* __restrict__ batch) {
    __shared__ alignas(16) __half As[BM][ASTR];   // [m][k]
    __shared__ alignas(16) __half Bs[BN][ASTR];   // [n][k] (transposed W)

    const __half* __restrict__ A = g_bufB;
    __half* __restrict__ C = g_bufA;

    int tid = threadIdx.x;
    int warpId = tid >> 5, lane = tid & 31;
    int g = lane >> 2, q = lane & 3;
    int warpM = warpId >> 2;          // 0..1  -> 64 rows each
    int warpN = warpId & 3;           // 0..3  -> 32 cols each
    int rowBase = blockIdx.x * BM;
    int colBase = blockIdx.y * BN;

    float acc[4][4][4];
#pragma unroll
    for (int mt = 0; mt < 4; mt++)
#pragma unroll
        for (int nt = 0; nt < 4; nt++)
#pragma unroll
            for (int i = 0; i < 4; i++) acc[mt][nt][i] = 0.0f;

    int aRow = tid >> 1;              // 0..127
    int aKoff = (tid & 1) * 16;       // halves
    int bN = tid & 127;
    int bKoff = (tid >> 7) * 16;

    for (int k0 = 0; k0 < K; k0 += BK) {
        // ---- A tile (fp16 global -> smem) ----
        int gr = rowBase + aRow;
        uint4 av0 = make_uint4(0, 0, 0, 0), av1 = av0;
        if (gr < Nn) {
            const uint4* ap = (const uint4*)(A + (size_t)gr * K + k0 + aKoff);
            av0 = ap[0]; av1 = ap[1];
        }
        *(uint4*)&As[aRow][aKoff] = av0;
        *(uint4*)&As[aRow][aKoff + 8] = av1;
        // ---- B tile: transpose + convert fp32 -> fp16 ----
        __half hl[16];
#pragma unroll
        for (int j = 0; j < 16; j++)
            hl[j] = __float2half_rn(W[(size_t)(k0 + bKoff + j) * Hh + colBase + bN]);
        *(uint4*)&Bs[bN][bKoff] = *(uint4*)&hl[0];
        *(uint4*)&Bs[bN][bKoff + 8] = *(uint4*)&hl[8];
        __syncthreads();

#pragma unroll
        for (int kk = 0; kk < 2; kk++) {
            int kb = kk * 16;
            unsigned afr[4][4];
#pragma unroll
            for (int mt = 0; mt < 4; mt++) {
                int m = warpM * 64 + mt * 16;
                afr[mt][0] = *(const unsigned*)&As[m + g][kb + 2 * q];
                afr[mt][1] = *(const unsigned*)&As[m + g + 8][kb + 2 * q];
                afr[mt][2] = *(const unsigned*)&As[m + g][kb + 2 * q + 8];
                afr[mt][3] = *(const unsigned*)&As[m + g + 8][kb + 2 * q + 8];
            }
#pragma unroll
            for (int nt = 0; nt < 4; nt++) {
                int n = warpN * 32 + nt * 8;
                unsigned bfr[2];
                bfr[0] = *(const unsigned*)&Bs[n + g][kb + 2 * q];
                bfr[1] = *(const unsigned*)&Bs[n + g][kb + 2 * q + 8];
#pragma unroll
                for (int mt = 0; mt < 4; mt++)
                    mma_f16(acc[mt][nt], afr[mt], bfr);
            }
        }
        __syncthreads();
    }

    // ---- epilogue ----
#pragma unroll
    for (int mt = 0; mt < 4; mt++) {
        int r0 = rowBase + warpM * 64 + mt * 16 + g;
        int r1 = r0 + 8;
        bool ok0 = r0 < Nn, ok1 = r1 < Nn;
        float sc0 = (ok0 && scaleFlag) ? g_dinv[r0] : 1.0f;
        float sc1 = (ok1 && scaleFlag) ? g_dinv[r1] : 1.0f;
        int gb0 = (ok0 && poolFlag) ? batch[r0] : 0;
        int gb1 = (ok1 && poolFlag) ? batch[r1] : 0;
#pragma unroll
        for (int nt = 0; nt < 4; nt++) {
            int c = colBase + warpN * 32 + nt * 8 + 2 * q;
            float bs0 = bias[c], bs1 = bias[c + 1];
            float v00 = fmaxf(acc[mt][nt][0] + bs0, 0.0f) * sc0;
            float v01 = fmaxf(acc[mt][nt][1] + bs1, 0.0f) * sc0;
            float v10 = fmaxf(acc[mt][nt][2] + bs0, 0.0f) * sc1;
            float v11 = fmaxf(acc[mt][nt][3] + bs1, 0.0f) * sc1;
            if (poolFlag) {
                if (ok0) {
                    atomicAdd(&g_pool[gb0 * Hh + c], v00);
                    atomicAdd(&g_pool[gb0 * Hh + c + 1], v01);
                }
                if (ok1) {
                    atomicAdd(&g_pool[gb1 * Hh + c], v10);
                    atomicAdd(&g_pool[gb1 * Hh + c + 1], v11);
                }
            } else {
                if (ok0) {
                    __half2 h = __floats2half2_rn(v00, v01);
                    *(__half2*)&C[(size_t)r0 * Hh + c] = h;
                }
                if (ok1) {
                    __half2 h = __floats2half2_rn(v10, v11);
                    *(__half2*)&C[(size_t)r1 * Hh + c] = h;
                }
            }
        }
    }
}

// ---------------- output head -------------------------------------------------
__global__ void out_kernel(const float* __restrict__ Wout,
                           const float* __restrict__ bout,
                           float* __restrict__ out) {
    int g = blockIdx.x;
    int lane = threadIdx.x;                 // 32 threads
    float inv = 1.0f / fmaxf(g_cnts[g], 1.0f);
    float p[8];
#pragma unroll
    for (int v = 0; v < 8; v++) p[v] = g_pool[g * Hh + v * 32 + lane] * inv;
#pragma unroll
    for (int t = 0; t < Tt; t++) {
        float s = 0.0f;
#pragma unroll
        for (int v = 0; v < 8; v++) s += p[v] * Wout[(v * 32 + lane) * Tt + t];
#pragma unroll
        for (int off = 16; off; off >>= 1) s += __shfl_down_sync(0xffffffffu, s, off);
        if (lane == 0) out[g * Tt + t] = s + bout[t];
    }
}

// ---------------- launch -----------------------------------------------------
extern "C" void kernel_launch(void* const* d_in, const int* in_sizes, int n_in,
                              void* d_out, int out_size) {
    const float* x    = (const float*)d_in[0];
    const int*   ei   = (const int*)d_in[1];   // [2, E] int32
    const int*   bat  = (const int*)d_in[2];
    const float* W0 = (const float*)d_in[3];  const float* b0 = (const float*)d_in[4];
    const float* W1 = (const float*)d_in[5];  const float* b1 = (const float*)d_in[6];
    const float* W2 = (const float*)d_in[7];  const float* b2 = (const float*)d_in[8];
    const float* W3 = (const float*)d_in[9];  const float* b3 = (const float*)d_in[10];
    const float* Wout = (const float*)d_in[11]; const float* bout = (const float*)d_in[12];
    float* out = (float*)d_out;

    const int* src = ei;
    const int* dst = ei + Ee;

    // prep
    zero_kernel<<<(Gg * Hh + 255) / 256, 256>>>();
    hist_kernel<<<(Ee + 255) / 256, 256>>>(dst);
    scan1_kernel<<<NBLK, 256>>>();
    scan2_kernel<<<1, 256>>>();
    scan3_kernel<<<NBLK, 256>>>();
    fill_kernel<<<(Ee + 255) / 256, 256>>>(src, dst);
    dinv_kernel<<<(Nn + 255) / 256, 256>>>(bat);
    scale_x_kernel<<<(Nn * (Ff / 8) + 255) / 256, 256>>>((const float4*)x);

    dim3 gemmGrid((Nn + BM - 1) / BM, Hh / BN);
    int aggBlocks = (Nn * 32 + 255) / 256;

    // layer 0 (K=128)
    agg_kernel<4><<<aggBlocks, 256>>>();
    gemm_f16_kernel<<<gemmGrid, 256>>>(W0, b0, Ff, 1, 0, bat);
    // layer 1
    agg_kernel<8><<<aggBlocks, 256>>>();
    gemm_f16_kernel<<<gemmGrid, 256>>>(W1, b1, Hh, 1, 0, bat);
    // layer 2
    agg_kernel<8><<<aggBlocks, 256>>>();
    gemm_f16_kernel<<<gemmGrid, 256>>>(W2, b2, Hh, 1, 0, bat);
    // layer 3: no dinv pre-scale; fused mean-pool accumulation
    agg_kernel<8><<<aggBlocks, 256>>>();
    gemm_f16_kernel<<<gemmGrid, 256>>>(W3, b3, Hh, 0, 1, bat);

    // head
    out_kernel<<<Gg, 32>>>(Wout, bout, out);
}